// round 2
// baseline (speedup 1.0000x reference)
#include <cuda_runtime.h>

#define D 128
#define EB 16
#define MAXN 50176

// Scratch (static device allocations are allowed; runtime allocs are not)
__device__ float g_agg[MAXN * D];
__device__ float g_tsum[MAXN * 3];
__device__ float g_cnt[MAXN];

__device__ __forceinline__ float silu_f(float x) { return x / (1.0f + __expf(-x)); }

__device__ __forceinline__ float wred(float v) {
    v += __shfl_xor_sync(0xffffffffu, v, 16);
    v += __shfl_xor_sync(0xffffffffu, v, 8);
    v += __shfl_xor_sync(0xffffffffu, v, 4);
    v += __shfl_xor_sync(0xffffffffu, v, 2);
    v += __shfl_xor_sync(0xffffffffu, v, 1);
    return v;
}

__global__ void __launch_bounds__(256) zero_kernel(int N) {
    int i = blockIdx.x * blockDim.x + threadIdx.x;
    int stride = gridDim.x * blockDim.x;
    for (int k = i; k < N * D; k += stride) g_agg[k] = 0.0f;
    for (int k = i; k < N * 3; k += stride) g_tsum[k] = 0.0f;
    for (int k = i; k < N; k += stride) g_cnt[k] = 0.0f;
}

// ---- GEMM loop over swizzled s_mid ([k][e] float4-chunk XOR swizzle) ----
// chunk at position p of row k holds edge-group p ^ ((k>>1)&3)
#define MID_GEMM_LOOP(Wptr)                                              \
    for (int kk = 0; kk < D; kk += 8) {                                  \
        _Pragma("unroll")                                                \
        for (int u = 0; u < 8; u++) {                                    \
            const int k = kk + u;                                        \
            const int phi = (u >> 1) & 3;                                \
            float wv = __ldg((Wptr) + k * D);                            \
            const float4* xp = (const float4*)&s_mid[k * EB];            \
            _Pragma("unroll")                                            \
            for (int p = 0; p < 4; p++) {                                \
                float4 xv = xp[p];                                       \
                const int g4 = 4 * (p ^ phi);                            \
                acc[g4 + 0] = fmaf(xv.x, wv, acc[g4 + 0]);               \
                acc[g4 + 1] = fmaf(xv.y, wv, acc[g4 + 1]);               \
                acc[g4 + 2] = fmaf(xv.z, wv, acc[g4 + 2]);               \
                acc[g4 + 3] = fmaf(xv.w, wv, acc[g4 + 3]);               \
            }                                                            \
        }                                                                \
    }

// store 16 per-edge register values (column t) into swizzled s_mid row t
#define MID_STORE(vals)                                                  \
    {                                                                    \
        const int phiw = (t >> 1) & 3;                                   \
        float4* mp = (float4*)&s_mid[t * EB];                            \
        _Pragma("unroll")                                                \
        for (int g = 0; g < 4; g++) {                                    \
            mp[g ^ phiw] = make_float4((vals)[4 * g + 0], (vals)[4 * g + 1], \
                                       (vals)[4 * g + 2], (vals)[4 * g + 3]); \
        }                                                                \
    }

__global__ void __launch_bounds__(128) edge_kernel(
    const float* __restrict__ h, const int* __restrict__ ei,
    const float* __restrict__ coord,
    const float* __restrict__ We1, const float* __restrict__ be1,
    const float* __restrict__ We2, const float* __restrict__ be2,
    const float* __restrict__ Watt, const float* __restrict__ batt,
    const float* __restrict__ Wc1, const float* __restrict__ bc1,
    const float* __restrict__ Wc2,
    float* __restrict__ out_ef, int E, int N)
{
    __shared__ __align__(16) float s_in[257 * EB];
    __shared__ __align__(16) float s_mid[D * EB];
    __shared__ float s_red[4 * EB];
    __shared__ float s_sc[EB];
    __shared__ float s_cd[EB * 3];
    __shared__ int s_row[EB], s_col[EB];

    const int t = threadIdx.x;
    const int lane = t & 31;
    const int warp = t >> 5;
    const int e0 = blockIdx.x * EB;

    if (t < EB) {
        int ee = min(e0 + t, E - 1);
        s_row[t] = ei[ee];
        s_col[t] = ei[(size_t)E + ee];
    }
    __syncthreads();

    if (t < EB) {
        int r = s_row[t], c = s_col[t];
        float dx = coord[r * 3 + 0] - coord[c * 3 + 0];
        float dy = coord[r * 3 + 1] - coord[c * 3 + 1];
        float dz = coord[r * 3 + 2] - coord[c * 3 + 2];
        s_cd[t * 3 + 0] = dx; s_cd[t * 3 + 1] = dy; s_cd[t * 3 + 2] = dz;
        s_in[256 * EB + t] = dx * dx + dy * dy + dz * dz;
    }
    // gather h[row], h[col] into s_in[k][e] (conflict-free STS)
    {
        int e = t & (EB - 1);
        int kb = t / EB;  // 0..7
        int r = s_row[e], c = s_col[e];
        #pragma unroll
        for (int i = 0; i < 16; i++) {
            int k = kb + 8 * i;
            s_in[k * EB + e]         = h[(size_t)r * D + k];
            s_in[(128 + k) * EB + e] = h[(size_t)c * D + k];
        }
    }
    __syncthreads();

    float acc[EB];

    // ---- layer 1: [h_row | h_col | radial] @ We1 + be1 ----
    {
        float b = __ldg(&be1[t]);
        #pragma unroll
        for (int e = 0; e < EB; e++) acc[e] = b;
        const float* w = We1 + t;
        #pragma unroll 4
        for (int k = 0; k < 257; k++) {
            float wv = __ldg(w + k * D);
            const float4* xp = (const float4*)&s_in[k * EB];
            #pragma unroll
            for (int p = 0; p < 4; p++) {
                float4 xv = xp[p];
                acc[4 * p + 0] = fmaf(xv.x, wv, acc[4 * p + 0]);
                acc[4 * p + 1] = fmaf(xv.y, wv, acc[4 * p + 1]);
                acc[4 * p + 2] = fmaf(xv.z, wv, acc[4 * p + 2]);
                acc[4 * p + 3] = fmaf(xv.w, wv, acc[4 * p + 3]);
            }
        }
    }
    #pragma unroll
    for (int e = 0; e < EB; e++) acc[e] = silu_f(acc[e]);
    MID_STORE(acc);
    __syncthreads();

    // ---- layer 2: mid @ We2 + be2, silu ----
    {
        float b = __ldg(&be2[t]);
        #pragma unroll
        for (int e = 0; e < EB; e++) acc[e] = b;
        const float* w = We2 + t;
        MID_GEMM_LOOP(w);
    }
    #pragma unroll
    for (int e = 0; e < EB; e++) acc[e] = silu_f(acc[e]);  // acc = edge_feat (pre-att)

    // ---- attention: sigmoid(ef @ Watt + batt) ----
    {
        float wa = __ldg(&Watt[t]);
        #pragma unroll
        for (int e = 0; e < EB; e++) {
            float v = wred(acc[e] * wa);
            if (lane == 0) s_red[warp * EB + e] = v;
        }
    }
    __syncthreads();
    if (t < EB) {
        float v = s_red[0 * EB + t] + s_red[1 * EB + t] +
                  s_red[2 * EB + t] + s_red[3 * EB + t] + __ldg(&batt[0]);
        s_sc[t] = 1.0f / (1.0f + __expf(-v));
    }
    __syncthreads();
    #pragma unroll
    for (int e = 0; e < EB; e++) acc[e] *= s_sc[e];  // scaled edge_feat

    // store edge_feat output + scatter into node agg; also re-stage into s_mid
    MID_STORE(acc);
    #pragma unroll
    for (int e = 0; e < EB; e++) {
        int eg = e0 + e;
        if (eg < E) {
            out_ef[(size_t)eg * D + t] = acc[e];
            atomicAdd(&g_agg[(size_t)s_row[e] * D + t], acc[e]);
        }
    }
    __syncthreads();

    // ---- coord path: silu(ef @ Wc1 + bc1) @ Wc2 -> scalar per edge ----
    {
        float b = __ldg(&bc1[t]);
        #pragma unroll
        for (int e = 0; e < EB; e++) acc[e] = b;
        const float* w = Wc1 + t;
        MID_GEMM_LOOP(w);
    }
    {
        float wc2 = __ldg(&Wc2[t]);
        #pragma unroll
        for (int e = 0; e < EB; e++) {
            float v = wred(silu_f(acc[e]) * wc2);
            if (lane == 0) s_red[warp * EB + e] = v;
        }
    }
    __syncthreads();
    if (t < EB) {
        int eg = e0 + t;
        if (eg < E) {
            float cw = s_red[0 * EB + t] + s_red[1 * EB + t] +
                       s_red[2 * EB + t] + s_red[3 * EB + t];
            int r = s_row[t];
            #pragma unroll
            for (int q = 0; q < 3; q++) {
                float tr = s_cd[t * 3 + q] * cw;
                tr = fminf(fmaxf(tr, -10.0f), 10.0f);
                atomicAdd(&g_tsum[r * 3 + q], tr);
            }
            atomicAdd(&g_cnt[r], 1.0f);
        }
    }
}

__global__ void __launch_bounds__(128) node_kernel(
    const float* __restrict__ h, const float* __restrict__ coord,
    const float* __restrict__ Wn1, const float* __restrict__ bn1,
    const float* __restrict__ Wn2, const float* __restrict__ bn2,
    float* __restrict__ out_h, float* __restrict__ out_c, int N)
{
    __shared__ __align__(16) float s_in[256 * EB];
    __shared__ __align__(16) float s_mid[D * EB];
    const int t = threadIdx.x;
    const int n0 = blockIdx.x * EB;

    {
        int e = t & (EB - 1);
        int kb = t / EB;
        int n = min(n0 + e, N - 1);
        #pragma unroll
        for (int i = 0; i < 16; i++) {
            int k = kb + 8 * i;
            s_in[k * EB + e]         = h[(size_t)n * D + k];
            s_in[(128 + k) * EB + e] = g_agg[(size_t)n * D + k];
        }
    }
    __syncthreads();

    float acc[EB];
    {
        float b = __ldg(&bn1[t]);
        #pragma unroll
        for (int e = 0; e < EB; e++) acc[e] = b;
        const float* w = Wn1 + t;
        #pragma unroll 4
        for (int k = 0; k < 256; k++) {
            float wv = __ldg(w + k * D);
            const float4* xp = (const float4*)&s_in[k * EB];
            #pragma unroll
            for (int p = 0; p < 4; p++) {
                float4 xv = xp[p];
                acc[4 * p + 0] = fmaf(xv.x, wv, acc[4 * p + 0]);
                acc[4 * p + 1] = fmaf(xv.y, wv, acc[4 * p + 1]);
                acc[4 * p + 2] = fmaf(xv.z, wv, acc[4 * p + 2]);
                acc[4 * p + 3] = fmaf(xv.w, wv, acc[4 * p + 3]);
            }
        }
    }
    #pragma unroll
    for (int e = 0; e < EB; e++) acc[e] = silu_f(acc[e]);
    MID_STORE(acc);
    __syncthreads();

    {
        float b = __ldg(&bn2[t]);
        #pragma unroll
        for (int e = 0; e < EB; e++) acc[e] = b;
        const float* w = Wn2 + t;
        MID_GEMM_LOOP(w);
    }
    #pragma unroll
    for (int e = 0; e < EB; e++) {
        int n = n0 + e;
        if (n < N) out_h[(size_t)n * D + t] = h[(size_t)n * D + t] + acc[e];
    }

    if (t < EB) {
        int n = n0 + t;
        if (n < N) {
            float c = fmaxf(g_cnt[n], 1.0f);
            #pragma unroll
            for (int q = 0; q < 3; q++) {
                float m = g_tsum[n * 3 + q] / c;
                m = fminf(fmaxf(m, -10.0f), 10.0f);
                out_c[n * 3 + q] = coord[n * 3 + q] + m;
            }
        }
    }
}

extern "C" void kernel_launch(void* const* d_in, const int* in_sizes, int n_in,
                              void* d_out, int out_size) {
    const float* h     = (const float*)d_in[0];
    const int*   ei    = (const int*)d_in[1];
    const float* coord = (const float*)d_in[2];
    const float* We1  = (const float*)d_in[3];
    const float* be1  = (const float*)d_in[4];
    const float* We2  = (const float*)d_in[5];
    const float* be2  = (const float*)d_in[6];
    const float* Watt = (const float*)d_in[7];
    const float* batt = (const float*)d_in[8];
    const float* Wc1  = (const float*)d_in[9];
    const float* bc1  = (const float*)d_in[10];
    const float* Wc2  = (const float*)d_in[11];
    const float* Wn1  = (const float*)d_in[12];
    const float* bn1  = (const float*)d_in[13];
    const float* Wn2  = (const float*)d_in[14];
    const float* bn2  = (const float*)d_in[15];

    int N = in_sizes[0] / D;
    int E = in_sizes[1] / 2;

    float* out   = (float*)d_out;
    float* out_h = out;                       // [N, 128]
    float* out_c = out + (size_t)N * D;       // [N, 3]
    float* out_e = out_c + (size_t)N * 3;     // [E, 128]

    zero_kernel<<<1024, 256>>>(N);
    edge_kernel<<<(E + EB - 1) / EB, 128>>>(h, ei, coord, We1, be1, We2, be2,
                                            Watt, batt, Wc1, bc1, Wc2,
                                            out_e, E, N);
    node_kernel<<<(N + EB - 1) / EB, 128>>>(h, coord, Wn1, bn1, Wn2, bn2,
                                            out_h, out_c, N);
}

// round 3
// speedup vs baseline: 1.0540x; 1.0540x over previous
#include <cuda_runtime.h>

#define D 128
#define EB 16
#define MAXN 50176

typedef unsigned long long ull;

__device__ float g_agg[MAXN * D];
__device__ float g_tsum[MAXN * 3];
__device__ float g_cnt[MAXN];

__device__ __forceinline__ float silu_f(float x) { return x / (1.0f + __expf(-x)); }

__device__ __forceinline__ void fma2(ull& d, ull a, ull b) {
    asm("fma.rn.f32x2 %0, %1, %2, %0;" : "+l"(d) : "l"(a), "l"(b));
}
__device__ __forceinline__ ull pack2(float x, float y) {
    ull r;
    asm("mov.b64 %0, {%1, %2};" : "=l"(r) : "f"(x), "f"(y));
    return r;
}
__device__ __forceinline__ void unpack2(ull v, float& x, float& y) {
    asm("mov.b64 {%0, %1}, %2;" : "=f"(x), "=f"(y) : "l"(v));
}

__device__ __forceinline__ float wred(float v) {
    v += __shfl_xor_sync(0xffffffffu, v, 16);
    v += __shfl_xor_sync(0xffffffffu, v, 8);
    v += __shfl_xor_sync(0xffffffffu, v, 4);
    v += __shfl_xor_sync(0xffffffffu, v, 2);
    v += __shfl_xor_sync(0xffffffffu, v, 1);
    return v;
}

__global__ void __launch_bounds__(256) zero_kernel(int N) {
    int i = blockIdx.x * blockDim.x + threadIdx.x;
    int stride = gridDim.x * blockDim.x;
    for (int k = i; k < N * D; k += stride) g_agg[k] = 0.0f;
    for (int k = i; k < N * 3; k += stride) g_tsum[k] = 0.0f;
    for (int k = i; k < N; k += stride) g_cnt[k] = 0.0f;
}

// GEMM over un-swizzled s_in ([k][e]): pairs (2j,2j+1) packed as f32x2
#define IN_GEMM_K(SRC, k)                                                \
    {                                                                    \
        float wv = __ldg(w + (k) * D);                                   \
        ull w2 = pack2(wv, wv);                                          \
        const ulonglong2* xp = (const ulonglong2*)&(SRC)[(k) * EB];      \
        _Pragma("unroll")                                                \
        for (int p = 0; p < 4; p++) {                                    \
            ulonglong2 xv = xp[p];                                       \
            fma2(acc2[2 * p + 0], xv.x, w2);                             \
            fma2(acc2[2 * p + 1], xv.y, w2);                             \
        }                                                                \
    }

// GEMM over swizzled s_mid: float4 chunk at position p of row k holds group p^((k>>1)&3)
#define MID_GEMM_LOOP(Wptr)                                              \
    for (int kk = 0; kk < D; kk += 8) {                                  \
        _Pragma("unroll")                                                \
        for (int u = 0; u < 8; u++) {                                    \
            const int k = kk + u;                                        \
            const int phi = (u >> 1) & 3;                                \
            float wv = __ldg((Wptr) + k * D);                            \
            ull w2 = pack2(wv, wv);                                      \
            const ulonglong2* xp = (const ulonglong2*)&s_mid[k * EB];    \
            _Pragma("unroll")                                            \
            for (int p = 0; p < 4; p++) {                                \
                ulonglong2 xv = xp[p];                                   \
                const int g = p ^ phi;                                   \
                fma2(acc2[2 * g + 0], xv.x, w2);                         \
                fma2(acc2[2 * g + 1], xv.y, w2);                         \
            }                                                            \
        }                                                                \
    }

#define ACC_INIT(bv)                                                     \
    {                                                                    \
        ull b2 = pack2((bv), (bv));                                      \
        _Pragma("unroll")                                                \
        for (int j = 0; j < 8; j++) acc2[j] = b2;                        \
    }

#define ACC_UNPACK(dst)                                                  \
    _Pragma("unroll")                                                    \
    for (int j = 0; j < 8; j++) unpack2(acc2[j], (dst)[2 * j], (dst)[2 * j + 1]);

// store 16 per-edge register values (column t) into swizzled s_mid row t
#define MID_STORE(vals)                                                  \
    {                                                                    \
        const int phiw = (t >> 1) & 3;                                   \
        float4* mp = (float4*)&s_mid[t * EB];                            \
        _Pragma("unroll")                                                \
        for (int g = 0; g < 4; g++) {                                    \
            mp[g ^ phiw] = make_float4((vals)[4 * g + 0], (vals)[4 * g + 1], \
                                       (vals)[4 * g + 2], (vals)[4 * g + 3]); \
        }                                                                \
    }

__global__ void __launch_bounds__(128) edge_kernel(
    const float* __restrict__ h, const int* __restrict__ ei,
    const float* __restrict__ coord,
    const float* __restrict__ We1, const float* __restrict__ be1,
    const float* __restrict__ We2, const float* __restrict__ be2,
    const float* __restrict__ Watt, const float* __restrict__ batt,
    const float* __restrict__ Wc1, const float* __restrict__ bc1,
    const float* __restrict__ Wc2,
    float* __restrict__ out_ef, int E, int N)
{
    __shared__ __align__(16) float s_in[257 * EB];
    __shared__ __align__(16) float s_mid[D * EB];
    __shared__ float s_red[4 * EB];
    __shared__ float s_sc[EB];
    __shared__ float s_cd[EB * 3];
    __shared__ int s_row[EB], s_col[EB];

    const int t = threadIdx.x;
    const int lane = t & 31;
    const int warp = t >> 5;
    const int e0 = blockIdx.x * EB;

    if (t < EB) {
        int ee = min(e0 + t, E - 1);
        s_row[t] = ei[ee];
        s_col[t] = ei[(size_t)E + ee];
    }
    __syncthreads();

    if (t < EB) {
        int r = s_row[t], c = s_col[t];
        float dx = coord[r * 3 + 0] - coord[c * 3 + 0];
        float dy = coord[r * 3 + 1] - coord[c * 3 + 1];
        float dz = coord[r * 3 + 2] - coord[c * 3 + 2];
        s_cd[t * 3 + 0] = dx; s_cd[t * 3 + 1] = dy; s_cd[t * 3 + 2] = dz;
        s_in[256 * EB + t] = dx * dx + dy * dy + dz * dz;
    }
    {
        int e = t & (EB - 1);
        int kb = t / EB;  // 0..7
        int r = s_row[e], c = s_col[e];
        #pragma unroll
        for (int i = 0; i < 16; i++) {
            int k = kb + 8 * i;
            s_in[k * EB + e]         = h[(size_t)r * D + k];
            s_in[(128 + k) * EB + e] = h[(size_t)c * D + k];
        }
    }
    __syncthreads();

    ull acc2[8];
    float accf[EB];

    // ---- layer 1: [h_row | h_col | radial] @ We1 + be1 ----
    {
        ACC_INIT(__ldg(&be1[t]));
        const float* w = We1 + t;
        #pragma unroll 4
        for (int k = 0; k < 257; k++) IN_GEMM_K(s_in, k);
    }
    ACC_UNPACK(accf);
    #pragma unroll
    for (int e = 0; e < EB; e++) accf[e] = silu_f(accf[e]);
    MID_STORE(accf);
    __syncthreads();

    // ---- layer 2: mid @ We2 + be2, silu ----
    {
        ACC_INIT(__ldg(&be2[t]));
        const float* w = We2 + t;
        MID_GEMM_LOOP(w);
    }
    ACC_UNPACK(accf);
    #pragma unroll
    for (int e = 0; e < EB; e++) accf[e] = silu_f(accf[e]);  // edge_feat (pre-att)

    // ---- attention: sigmoid(ef @ Watt + batt) ----
    {
        float wa = __ldg(&Watt[t]);
        #pragma unroll
        for (int e = 0; e < EB; e++) {
            float v = wred(accf[e] * wa);
            if (lane == 0) s_red[warp * EB + e] = v;
        }
    }
    __syncthreads();
    if (t < EB) {
        float v = s_red[0 * EB + t] + s_red[1 * EB + t] +
                  s_red[2 * EB + t] + s_red[3 * EB + t] + __ldg(&batt[0]);
        s_sc[t] = 1.0f / (1.0f + __expf(-v));
    }
    __syncthreads();
    #pragma unroll
    for (int e = 0; e < EB; e++) accf[e] *= s_sc[e];  // scaled edge_feat

    MID_STORE(accf);
    #pragma unroll
    for (int e = 0; e < EB; e++) {
        int eg = e0 + e;
        if (eg < E) {
            out_ef[(size_t)eg * D + t] = accf[e];
            atomicAdd(&g_agg[(size_t)s_row[e] * D + t], accf[e]);
        }
    }
    __syncthreads();

    // ---- coord path: silu(ef @ Wc1 + bc1) @ Wc2 -> scalar per edge ----
    {
        ACC_INIT(__ldg(&bc1[t]));
        const float* w = Wc1 + t;
        MID_GEMM_LOOP(w);
    }
    ACC_UNPACK(accf);
    {
        float wc2 = __ldg(&Wc2[t]);
        #pragma unroll
        for (int e = 0; e < EB; e++) {
            float v = wred(silu_f(accf[e]) * wc2);
            if (lane == 0) s_red[warp * EB + e] = v;
        }
    }
    __syncthreads();
    if (t < EB) {
        int eg = e0 + t;
        if (eg < E) {
            float cw = s_red[0 * EB + t] + s_red[1 * EB + t] +
                       s_red[2 * EB + t] + s_red[3 * EB + t];
            int r = s_row[t];
            #pragma unroll
            for (int q = 0; q < 3; q++) {
                float tr = s_cd[t * 3 + q] * cw;
                tr = fminf(fmaxf(tr, -10.0f), 10.0f);
                atomicAdd(&g_tsum[r * 3 + q], tr);
            }
            atomicAdd(&g_cnt[r], 1.0f);
        }
    }
}

__global__ void __launch_bounds__(128) node_kernel(
    const float* __restrict__ h, const float* __restrict__ coord,
    const float* __restrict__ Wn1, const float* __restrict__ bn1,
    const float* __restrict__ Wn2, const float* __restrict__ bn2,
    float* __restrict__ out_h, float* __restrict__ out_c, int N)
{
    __shared__ __align__(16) float s_in[256 * EB];
    __shared__ __align__(16) float s_mid[D * EB];
    const int t = threadIdx.x;
    const int n0 = blockIdx.x * EB;

    {
        int e = t & (EB - 1);
        int kb = t / EB;
        int n = min(n0 + e, N - 1);
        #pragma unroll
        for (int i = 0; i < 16; i++) {
            int k = kb + 8 * i;
            s_in[k * EB + e]         = h[(size_t)n * D + k];
            s_in[(128 + k) * EB + e] = g_agg[(size_t)n * D + k];
        }
    }
    __syncthreads();

    ull acc2[8];
    float accf[EB];
    {
        ACC_INIT(__ldg(&bn1[t]));
        const float* w = Wn1 + t;
        #pragma unroll 4
        for (int k = 0; k < 256; k++) IN_GEMM_K(s_in, k);
    }
    ACC_UNPACK(accf);
    #pragma unroll
    for (int e = 0; e < EB; e++) accf[e] = silu_f(accf[e]);
    MID_STORE(accf);
    __syncthreads();

    {
        ACC_INIT(__ldg(&bn2[t]));
        const float* w = Wn2 + t;
        MID_GEMM_LOOP(w);
    }
    ACC_UNPACK(accf);
    #pragma unroll
    for (int e = 0; e < EB; e++) {
        int n = n0 + e;
        if (n < N) out_h[(size_t)n * D + t] = h[(size_t)n * D + t] + accf[e];
    }

    if (t < EB) {
        int n = n0 + t;
        if (n < N) {
            float c = fmaxf(g_cnt[n], 1.0f);
            #pragma unroll
            for (int q = 0; q < 3; q++) {
                float m = g_tsum[n * 3 + q] / c;
                m = fminf(fmaxf(m, -10.0f), 10.0f);
                out_c[n * 3 + q] = coord[n * 3 + q] + m;
            }
        }
    }
}

extern "C" void kernel_launch(void* const* d_in, const int* in_sizes, int n_in,
                              void* d_out, int out_size) {
    const float* h     = (const float*)d_in[0];
    const int*   ei    = (const int*)d_in[1];
    const float* coord = (const float*)d_in[2];
    const float* We1  = (const float*)d_in[3];
    const float* be1  = (const float*)d_in[4];
    const float* We2  = (const float*)d_in[5];
    const float* be2  = (const float*)d_in[6];
    const float* Watt = (const float*)d_in[7];
    const float* batt = (const float*)d_in[8];
    const float* Wc1  = (const float*)d_in[9];
    const float* bc1  = (const float*)d_in[10];
    const float* Wc2  = (const float*)d_in[11];
    const float* Wn1  = (const float*)d_in[12];
    const float* bn1  = (const float*)d_in[13];
    const float* Wn2  = (const float*)d_in[14];
    const float* bn2  = (const float*)d_in[15];

    int N = in_sizes[0] / D;
    int E = in_sizes[1] / 2;

    float* out   = (float*)d_out;
    float* out_h = out;                       // [N, 128]
    float* out_c = out + (size_t)N * D;       // [N, 3]
    float* out_e = out_c + (size_t)N * 3;     // [E, 128]

    zero_kernel<<<1024, 256>>>(N);
    edge_kernel<<<(E + EB - 1) / EB, 128>>>(h, ei, coord, We1, be1, We2, be2,
                                            Watt, batt, Wc1, bc1, Wc2,
                                            out_e, E, N);
    node_kernel<<<(N + EB - 1) / EB, 128>>>(h, coord, Wn1, bn1, Wn2, bn2,
                                            out_h, out_c, N);
}

// round 6
// speedup vs baseline: 1.7077x; 1.6202x over previous
#include <cuda_runtime.h>
#include <cuda_bf16.h>

#define D 128
#define EB 16
#define MAXN 50176
#define TM 128

// ---- dynamic SMEM layout ----
#define SM_A     0          // A hi: 4 chunks x [128][64] bf16 (16KB each)
#define SM_AL    65536      // A lo
#define SM_B     131072     // B hi chunk [128][64] bf16
#define SM_BL    147456     // B lo
#define SM_ROWI  163840
#define SM_COLI  164352
#define SM_RADI  164864
#define SM_CDI   165376
#define SMEM_EDGE 166912
#define SMEM_NODE 163840

typedef unsigned uns;

__device__ float g_agg[MAXN * D];
__device__ float g_tsum[MAXN * 3];
__device__ float g_cnt[MAXN];

// prepped W^T bf16 hi/lo: [chunk][n=128][kc=64]
__device__ __nv_bfloat16 g_W1H[4 * 8192], g_W1L[4 * 8192];
__device__ __nv_bfloat16 g_W2H[2 * 8192], g_W2L[2 * 8192];
__device__ __nv_bfloat16 g_WcH[2 * 8192], g_WcL[2 * 8192];
__device__ __nv_bfloat16 g_N1H[4 * 8192], g_N1L[4 * 8192];
__device__ __nv_bfloat16 g_N2H[2 * 8192], g_N2L[2 * 8192];
__device__ float g_W1last[128];

__device__ __forceinline__ float silu_f(float x) { return x / (1.0f + __expf(-x)); }
__device__ __forceinline__ uns sw128(uns o) { return o ^ ((o >> 3) & 0x70); }

__device__ __forceinline__ uns smem_u32(const void* p) {
    uns a;
    asm("{ .reg .u64 t; cvta.to.shared.u64 t, %1; cvt.u32.u64 %0, t; }" : "=r"(a) : "l"(p));
    return a;
}
__device__ __forceinline__ void split2(float a, float b, uns& hi, uns& lo) {
    uns p;
    asm("cvt.rn.satfinite.bf16x2.f32 %0, %1, %2;" : "=r"(p) : "f"(b), "f"(a));
    float f0 = __uint_as_float(p << 16);
    float f1 = __uint_as_float(p & 0xFFFF0000u);
    uns q;
    asm("cvt.rn.satfinite.bf16x2.f32 %0, %1, %2;" : "=r"(q) : "f"(b - f1), "f"(a - f0));
    hi = p; lo = q;
}
__device__ __forceinline__ void ldm_x4(uns r[4], uns addr) {
    asm volatile("ldmatrix.sync.aligned.m8n8.x4.shared.b16 {%0,%1,%2,%3}, [%4];"
        : "=r"(r[0]), "=r"(r[1]), "=r"(r[2]), "=r"(r[3]) : "r"(addr));
}
__device__ __forceinline__ void ldm_x2(uns r[2], uns addr) {
    asm volatile("ldmatrix.sync.aligned.m8n8.x2.shared.b16 {%0,%1}, [%2];"
        : "=r"(r[0]), "=r"(r[1]) : "r"(addr));
}
__device__ __forceinline__ void mma16816(float c[4], const uns a[4], const uns b[2]) {
    asm volatile("mma.sync.aligned.m16n8k16.row.col.f32.bf16.bf16.f32 "
        "{%0,%1,%2,%3}, {%4,%5,%6,%7}, {%8,%9}, {%0,%1,%2,%3};"
        : "+f"(c[0]), "+f"(c[1]), "+f"(c[2]), "+f"(c[3])
        : "r"(a[0]), "r"(a[1]), "r"(a[2]), "r"(a[3]), "r"(b[0]), "r"(b[1]));
}

// ------------------------------------------------------------------
__global__ void __launch_bounds__(256) zero_kernel(int N) {
    int i = blockIdx.x * blockDim.x + threadIdx.x;
    int stride = gridDim.x * blockDim.x;
    for (int k = i; k < N * D; k += stride) g_agg[k] = 0.0f;
    for (int k = i; k < N * 3; k += stride) g_tsum[k] = 0.0f;
    for (int k = i; k < N; k += stride) g_cnt[k] = 0.0f;
}

__global__ void __launch_bounds__(512) prep_kernel(
    const float* __restrict__ We1, const float* __restrict__ We2,
    const float* __restrict__ Wc1, const float* __restrict__ Wn1,
    const float* __restrict__ Wn2)
{
    int id = blockIdx.x * blockDim.x + threadIdx.x;  // 0..32767
    int c = id >> 13, r = id & 8191, n = r >> 6, kc = r & 63;
    int src = (c * 64 + kc) * 128 + n;
    {
        float f = We1[src];
        __nv_bfloat16 hv = __float2bfloat16(f);
        g_W1H[id] = hv; g_W1L[id] = __float2bfloat16(f - __bfloat162float(hv));
        float fn = Wn1[src];
        __nv_bfloat16 hn = __float2bfloat16(fn);
        g_N1H[id] = hn; g_N1L[id] = __float2bfloat16(fn - __bfloat162float(hn));
    }
    if (id < 2 * 8192) {
        float f = We2[src];
        __nv_bfloat16 hv = __float2bfloat16(f);
        g_W2H[id] = hv; g_W2L[id] = __float2bfloat16(f - __bfloat162float(hv));
        float g = Wc1[src];
        __nv_bfloat16 hg = __float2bfloat16(g);
        g_WcH[id] = hg; g_WcL[id] = __float2bfloat16(g - __bfloat162float(hg));
        float fn = Wn2[src];
        __nv_bfloat16 hn = __float2bfloat16(fn);
        g_N2H[id] = hn; g_N2L[id] = __float2bfloat16(fn - __bfloat162float(hn));
    }
    if (id < 128) g_W1last[id] = We1[256 * 128 + id];
}

// one GEMM layer: C[128 x 128] += A[128 x nch*64] * W^T, 3-chain bf16 hi/lo
__device__ __forceinline__ void run_layer(
    char* sm, uns su, int t, int w, int l,
    const __nv_bfloat16* gH, const __nv_bfloat16* gL,
    int nch, float acc[16][4])
{
    #pragma unroll
    for (int nt = 0; nt < 16; nt++)
        #pragma unroll
        for (int j = 0; j < 4; j++) acc[nt][j] = 0.0f;

    const uns a_off = (uns)((w * 16 + (l & 15)) * 128 + (l >> 4) * 16);
    const uns b_row = (uns)((l & 7) * 128 + ((l >> 3) & 1) * 16);

    for (int c = 0; c < nch; c++) {
        __syncthreads();
        const uint4* srcH = (const uint4*)(gH + (size_t)c * 8192);
        const uint4* srcL = (const uint4*)(gL + (size_t)c * 8192);
        for (int i = t; i < 1024; i += 256) {
            uns dst = sw128((uns)((i >> 3) * 128 + (i & 7) * 16));
            *(uint4*)(sm + SM_B + dst) = __ldg(srcH + i);
            *(uint4*)(sm + SM_BL + dst) = __ldg(srcL + i);
        }
        __syncthreads();
        uns aB = su + SM_A + c * 16384;
        uns aBL = su + SM_AL + c * 16384;
        #pragma unroll
        for (int ks = 0; ks < 4; ks++) {
            uns ah[4], al[4];
            uns asw = sw128(a_off + ks * 32);
            ldm_x4(ah, aB + asw);
            ldm_x4(al, aBL + asw);
            #pragma unroll
            for (int nt = 0; nt < 16; nt++) {
                uns bh[2], bl[2];
                uns bsw = sw128(b_row + (uns)(nt * 1024) + ks * 32);
                ldm_x2(bh, su + SM_B + bsw);
                ldm_x2(bl, su + SM_BL + bsw);
                mma16816(acc[nt], ah, bh);
                mma16816(acc[nt], al, bh);
                mma16816(acc[nt], ah, bl);
            }
        }
    }
    __syncthreads();
}

__global__ void __launch_bounds__(256, 1) edge_tc_kernel(
    const float* __restrict__ h, const int* __restrict__ ei,
    const float* __restrict__ coord,
    const float* __restrict__ be1, const float* __restrict__ be2,
    const float* __restrict__ Watt, const float* __restrict__ batt,
    const float* __restrict__ bc1, const float* __restrict__ Wc2,
    float* __restrict__ out_ef, int E)
{
    extern __shared__ __align__(1024) char sm[];
    const uns su = smem_u32(sm);
    const int t = threadIdx.x;
    const int w = t >> 5, l = t & 31;
    const int e0 = blockIdx.x * TM;

    int* s_row = (int*)(sm + SM_ROWI);
    int* s_col = (int*)(sm + SM_COLI);
    float* s_rad = (float*)(sm + SM_RADI);
    float* s_cd = (float*)(sm + SM_CDI);

    if (t < TM) {
        int e = e0 + t;
        int r = ei[e], c = ei[(size_t)E + e];
        s_row[t] = r; s_col[t] = c;
        float dx = coord[r * 3 + 0] - coord[c * 3 + 0];
        float dy = coord[r * 3 + 1] - coord[c * 3 + 1];
        float dz = coord[r * 3 + 2] - coord[c * 3 + 2];
        s_cd[t * 3 + 0] = dx; s_cd[t * 3 + 1] = dy; s_cd[t * 3 + 2] = dz;
        s_rad[t] = dx * dx + dy * dy + dz * dz;
    }
    __syncthreads();

    // gather A1: vrow t: e = t&127, half = t>>7 (h[row] | h[col])
    {
        int e = t & 127, half = t >> 7;
        int r = half ? s_col[e] : s_row[e];
        const float4* src = (const float4*)(h + (size_t)r * 128);
        #pragma unroll 8
        for (int i = 0; i < 32; i++) {
            float4 f = __ldg(src + i);
            uns hA, lA, hB, lB;
            split2(f.x, f.y, hA, lA);
            split2(f.z, f.w, hB, lB);
            int k = i * 4;
            int ch = 2 * half + (k >> 6);
            uns o = sw128((uns)(e * 128 + (k & 63) * 2));
            *(uint2*)(sm + SM_A + ch * 16384 + o) = make_uint2(hA, hB);
            *(uint2*)(sm + SM_AL + ch * 16384 + o) = make_uint2(lA, lB);
        }
    }

    const int g = l >> 2, tq = l & 3;
    const int r0 = w * 16 + g, r1 = r0 + 8;
    float acc[16][4];

    // ===== layer1 =====
    run_layer(sm, su, t, w, l, g_W1H, g_W1L, 4, acc);
    {
        float rad0 = s_rad[r0], rad1 = s_rad[r1];
        #pragma unroll
        for (int nt = 0; nt < 16; nt++) {
            int c0 = nt * 8 + 2 * tq;
            float w0 = g_W1last[c0], w1 = g_W1last[c0 + 1];
            float b0 = __ldg(be1 + c0), b1 = __ldg(be1 + c0 + 1);
            float x0 = silu_f(acc[nt][0] + b0 + rad0 * w0);
            float x1 = silu_f(acc[nt][1] + b1 + rad0 * w1);
            float x2 = silu_f(acc[nt][2] + b0 + rad1 * w0);
            float x3 = silu_f(acc[nt][3] + b1 + rad1 * w1);
            uns h0, l0, h1, l1;
            split2(x0, x1, h0, l0);
            split2(x2, x3, h1, l1);
            int ch = c0 >> 6;
            uns o0 = sw128((uns)(r0 * 128 + (c0 & 63) * 2));
            uns o1 = sw128((uns)(r1 * 128 + (c0 & 63) * 2));
            *(uns*)(sm + SM_A + ch * 16384 + o0) = h0;
            *(uns*)(sm + SM_AL + ch * 16384 + o0) = l0;
            *(uns*)(sm + SM_A + ch * 16384 + o1) = h1;
            *(uns*)(sm + SM_AL + ch * 16384 + o1) = l1;
        }
    }

    // ===== layer2 + attention =====
    run_layer(sm, su, t, w, l, g_W2H, g_W2L, 2, acc);
    {
        float d0 = 0.0f, d1 = 0.0f;
        #pragma unroll
        for (int nt = 0; nt < 16; nt++) {
            int c0 = nt * 8 + 2 * tq;
            float b0 = __ldg(be2 + c0), b1 = __ldg(be2 + c0 + 1);
            float wa0 = __ldg(Watt + c0), wa1 = __ldg(Watt + c0 + 1);
            acc[nt][0] = silu_f(acc[nt][0] + b0);
            acc[nt][1] = silu_f(acc[nt][1] + b1);
            acc[nt][2] = silu_f(acc[nt][2] + b0);
            acc[nt][3] = silu_f(acc[nt][3] + b1);
            d0 += acc[nt][0] * wa0 + acc[nt][1] * wa1;
            d1 += acc[nt][2] * wa0 + acc[nt][3] * wa1;
        }
        d0 += __shfl_xor_sync(0xffffffffu, d0, 1);
        d0 += __shfl_xor_sync(0xffffffffu, d0, 2);
        d1 += __shfl_xor_sync(0xffffffffu, d1, 1);
        d1 += __shfl_xor_sync(0xffffffffu, d1, 2);
        float bt = __ldg(batt);
        float att0 = 1.0f / (1.0f + __expf(-(d0 + bt)));
        float att1 = 1.0f / (1.0f + __expf(-(d1 + bt)));
        int ra = s_row[r0], rb = s_row[r1];
        float* oA = out_ef + (size_t)(e0 + r0) * 128;
        float* oB = out_ef + (size_t)(e0 + r1) * 128;
        #pragma unroll
        for (int nt = 0; nt < 16; nt++) {
            int c0 = nt * 8 + 2 * tq;
            float x0 = acc[nt][0] * att0, x1 = acc[nt][1] * att0;
            float x2 = acc[nt][2] * att1, x3 = acc[nt][3] * att1;
            *(float2*)(oA + c0) = make_float2(x0, x1);
            *(float2*)(oB + c0) = make_float2(x2, x3);
            atomicAdd(&g_agg[(size_t)ra * 128 + c0], x0);
            atomicAdd(&g_agg[(size_t)ra * 128 + c0 + 1], x1);
            atomicAdd(&g_agg[(size_t)rb * 128 + c0], x2);
            atomicAdd(&g_agg[(size_t)rb * 128 + c0 + 1], x3);
            uns h0, l0, h1, l1;
            split2(x0, x1, h0, l0);
            split2(x2, x3, h1, l1);
            int ch = c0 >> 6;
            uns o0 = sw128((uns)(r0 * 128 + (c0 & 63) * 2));
            uns o1 = sw128((uns)(r1 * 128 + (c0 & 63) * 2));
            *(uns*)(sm + SM_A + ch * 16384 + o0) = h0;
            *(uns*)(sm + SM_AL + ch * 16384 + o0) = l0;
            *(uns*)(sm + SM_A + ch * 16384 + o1) = h1;
            *(uns*)(sm + SM_AL + ch * 16384 + o1) = l1;
        }
    }

    // ===== layer3 (coord) =====
    run_layer(sm, su, t, w, l, g_WcH, g_WcL, 2, acc);
    {
        float d0 = 0.0f, d1 = 0.0f;
        #pragma unroll
        for (int nt = 0; nt < 16; nt++) {
            int c0 = nt * 8 + 2 * tq;
            float b0 = __ldg(bc1 + c0), b1 = __ldg(bc1 + c0 + 1);
            float wc0 = __ldg(Wc2 + c0), wc1 = __ldg(Wc2 + c0 + 1);
            d0 += silu_f(acc[nt][0] + b0) * wc0 + silu_f(acc[nt][1] + b1) * wc1;
            d1 += silu_f(acc[nt][2] + b0) * wc0 + silu_f(acc[nt][3] + b1) * wc1;
        }
        d0 += __shfl_xor_sync(0xffffffffu, d0, 1);
        d0 += __shfl_xor_sync(0xffffffffu, d0, 2);
        d1 += __shfl_xor_sync(0xffffffffu, d1, 1);
        d1 += __shfl_xor_sync(0xffffffffu, d1, 2);
        if (tq == 0) {
            int rows[2] = {r0, r1};
            float cws[2] = {d0, d1};
            #pragma unroll
            for (int i = 0; i < 2; i++) {
                int rr = rows[i];
                int rn = s_row[rr];
                float cw = cws[i];
                #pragma unroll
                for (int q = 0; q < 3; q++) {
                    float tr = s_cd[rr * 3 + q] * cw;
                    tr = fminf(fmaxf(tr, -10.0f), 10.0f);
                    atomicAdd(&g_tsum[rn * 3 + q], tr);
                }
                atomicAdd(&g_cnt[rn], 1.0f);
            }
        }
    }
}

__global__ void __launch_bounds__(256, 1) node_tc_kernel(
    const float* __restrict__ h, const float* __restrict__ coord,
    const float* __restrict__ bn1, const float* __restrict__ bn2,
    float* __restrict__ out_h, float* __restrict__ out_c, int N)
{
    extern __shared__ __align__(1024) char sm[];
    const uns su = smem_u32(sm);
    const int t = threadIdx.x;
    const int w = t >> 5, l = t & 31;
    const int n0 = blockIdx.x * TM;

    // gather: vrow t: node n0+(t&127); halves h | g_agg
    {
        int e = t & 127, half = t >> 7;
        int n = min(n0 + e, N - 1);
        const float4* src = half ? (const float4*)(g_agg + (size_t)n * 128)
                                 : (const float4*)(h + (size_t)n * 128);
        #pragma unroll 8
        for (int i = 0; i < 32; i++) {
            float4 f = __ldg(src + i);
            uns hA, lA, hB, lB;
            split2(f.x, f.y, hA, lA);
            split2(f.z, f.w, hB, lB);
            int k = i * 4;
            int ch = 2 * half + (k >> 6);
            uns o = sw128((uns)(e * 128 + (k & 63) * 2));
            *(uint2*)(sm + SM_A + ch * 16384 + o) = make_uint2(hA, hB);
            *(uint2*)(sm + SM_AL + ch * 16384 + o) = make_uint2(lA, lB);
        }
    }

    const int g = l >> 2, tq = l & 3;
    const int r0 = w * 16 + g, r1 = r0 + 8;
    float acc[16][4];

    run_layer(sm, su, t, w, l, g_N1H, g_N1L, 4, acc);
    {
        #pragma unroll
        for (int nt = 0; nt < 16; nt++) {
            int c0 = nt * 8 + 2 * tq;
            float b0 = __ldg(bn1 + c0), b1 = __ldg(bn1 + c0 + 1);
            float x0 = silu_f(acc[nt][0] + b0);
            float x1 = silu_f(acc[nt][1] + b1);
            float x2 = silu_f(acc[nt][2] + b0);
            float x3 = silu_f(acc[nt][3] + b1);
            uns h0, l0, h1, l1;
            split2(x0, x1, h0, l0);
            split2(x2, x3, h1, l1);
            int ch = c0 >> 6;
            uns o0 = sw128((uns)(r0 * 128 + (c0 & 63) * 2));
            uns o1 = sw128((uns)(r1 * 128 + (c0 & 63) * 2));
            *(uns*)(sm + SM_A + ch * 16384 + o0) = h0;
            *(uns*)(sm + SM_AL + ch * 16384 + o0) = l0;
            *(uns*)(sm + SM_A + ch * 16384 + o1) = h1;
            *(uns*)(sm + SM_AL + ch * 16384 + o1) = l1;
        }
    }

    run_layer(sm, su, t, w, l, g_N2H, g_N2L, 2, acc);
    {
        int nA = n0 + r0, nB = n0 + r1;
        #pragma unroll
        for (int nt = 0; nt < 16; nt++) {
            int c0 = nt * 8 + 2 * tq;
            float b0 = __ldg(bn2 + c0), b1 = __ldg(bn2 + c0 + 1);
            if (nA < N) {
                float2 hv = *(const float2*)(h + (size_t)nA * 128 + c0);
                *(float2*)(out_h + (size_t)nA * 128 + c0) =
                    make_float2(hv.x + acc[nt][0] + b0, hv.y + acc[nt][1] + b1);
            }
            if (nB < N) {
                float2 hv = *(const float2*)(h + (size_t)nB * 128 + c0);
                *(float2*)(out_h + (size_t)nB * 128 + c0) =
                    make_float2(hv.x + acc[nt][2] + b0, hv.y + acc[nt][3] + b1);
            }
        }
    }

    if (t < TM) {
        int n = n0 + t;
        if (n < N) {
            float c = fmaxf(g_cnt[n], 1.0f);
            #pragma unroll
            for (int q = 0; q < 3; q++) {
                float m = g_tsum[n * 3 + q] / c;
                m = fminf(fmaxf(m, -10.0f), 10.0f);
                out_c[n * 3 + q] = coord[n * 3 + q] + m;
            }
        }
    }
}

// ------- scalar remainder edge kernel (last E % 128 edges) -------
__device__ __forceinline__ float wred(float v) {
    v += __shfl_xor_sync(0xffffffffu, v, 16);
    v += __shfl_xor_sync(0xffffffffu, v, 8);
    v += __shfl_xor_sync(0xffffffffu, v, 4);
    v += __shfl_xor_sync(0xffffffffu, v, 2);
    v += __shfl_xor_sync(0xffffffffu, v, 1);
    return v;
}

__global__ void __launch_bounds__(128) edge_rem_kernel(
    const float* __restrict__ h, const int* __restrict__ ei,
    const float* __restrict__ coord,
    const float* __restrict__ We1, const float* __restrict__ be1,
    const float* __restrict__ We2, const float* __restrict__ be2,
    const float* __restrict__ Watt, const float* __restrict__ batt,
    const float* __restrict__ Wc1, const float* __restrict__ bc1,
    const float* __restrict__ Wc2,
    float* __restrict__ out_ef, int E, int e_base)
{
    __shared__ __align__(16) float s_in[257 * EB];
    __shared__ __align__(16) float s_mid[D * EB];
    __shared__ float s_red[4 * EB];
    __shared__ float s_sc[EB];
    __shared__ float s_cd2[EB * 3];
    __shared__ int s_row[EB], s_col[EB];

    const int t = threadIdx.x;
    const int lane = t & 31;
    const int warp = t >> 5;
    const int e0 = e_base + blockIdx.x * EB;

    if (t < EB) {
        int ee = min(e0 + t, E - 1);
        s_row[t] = ei[ee];
        s_col[t] = ei[(size_t)E + ee];
    }
    __syncthreads();
    if (t < EB) {
        int r = s_row[t], c = s_col[t];
        float dx = coord[r * 3 + 0] - coord[c * 3 + 0];
        float dy = coord[r * 3 + 1] - coord[c * 3 + 1];
        float dz = coord[r * 3 + 2] - coord[c * 3 + 2];
        s_cd2[t * 3 + 0] = dx; s_cd2[t * 3 + 1] = dy; s_cd2[t * 3 + 2] = dz;
        s_in[256 * EB + t] = dx * dx + dy * dy + dz * dz;
    }
    {
        int e = t & (EB - 1);
        int kb = t / EB;
        int r = s_row[e], c = s_col[e];
        #pragma unroll
        for (int i = 0; i < 16; i++) {
            int k = kb + 8 * i;
            s_in[k * EB + e]         = h[(size_t)r * D + k];
            s_in[(128 + k) * EB + e] = h[(size_t)c * D + k];
        }
    }
    __syncthreads();

    float acc[EB];
    {
        float b = __ldg(&be1[t]);
        #pragma unroll
        for (int e = 0; e < EB; e++) acc[e] = b;
        const float* wp = We1 + t;
        for (int k = 0; k < 257; k++) {
            float wv = __ldg(wp + k * D);
            #pragma unroll
            for (int e = 0; e < EB; e++) acc[e] = fmaf(s_in[k * EB + e], wv, acc[e]);
        }
    }
    #pragma unroll
    for (int e = 0; e < EB; e++) acc[e] = silu_f(acc[e]);
    __syncthreads();
    #pragma unroll
    for (int e = 0; e < EB; e++) s_mid[t * EB + e] = acc[e];
    __syncthreads();

    {
        float b = __ldg(&be2[t]);
        #pragma unroll
        for (int e = 0; e < EB; e++) acc[e] = b;
        const float* wp = We2 + t;
        for (int k = 0; k < D; k++) {
            float wv = __ldg(wp + k * D);
            #pragma unroll
            for (int e = 0; e < EB; e++) acc[e] = fmaf(s_mid[k * EB + e], wv, acc[e]);
        }
    }
    #pragma unroll
    for (int e = 0; e < EB; e++) acc[e] = silu_f(acc[e]);

    {
        float wa = __ldg(&Watt[t]);
        #pragma unroll
        for (int e = 0; e < EB; e++) {
            float v = wred(acc[e] * wa);
            if (lane == 0) s_red[warp * EB + e] = v;
        }
    }
    __syncthreads();
    if (t < EB) {
        float v = s_red[0 * EB + t] + s_red[1 * EB + t] +
                  s_red[2 * EB + t] + s_red[3 * EB + t] + __ldg(&batt[0]);
        s_sc[t] = 1.0f / (1.0f + __expf(-v));
    }
    __syncthreads();
    #pragma unroll
    for (int e = 0; e < EB; e++) acc[e] *= s_sc[e];

    __syncthreads();
    #pragma unroll
    for (int e = 0; e < EB; e++) s_mid[t * EB + e] = acc[e];
    #pragma unroll
    for (int e = 0; e < EB; e++) {
        int eg = e0 + e;
        if (eg < E) {
            out_ef[(size_t)eg * D + t] = acc[e];
            atomicAdd(&g_agg[(size_t)s_row[e] * D + t], acc[e]);
        }
    }
    __syncthreads();

    {
        float b = __ldg(&bc1[t]);
        #pragma unroll
        for (int e = 0; e < EB; e++) acc[e] = b;
        const float* wp = Wc1 + t;
        for (int k = 0; k < D; k++) {
            float wv = __ldg(wp + k * D);
            #pragma unroll
            for (int e = 0; e < EB; e++) acc[e] = fmaf(s_mid[k * EB + e], wv, acc[e]);
        }
    }
    {
        float wc2 = __ldg(&Wc2[t]);
        #pragma unroll
        for (int e = 0; e < EB; e++) {
            float v = wred(silu_f(acc[e]) * wc2);
            if (lane == 0) s_red[warp * EB + e] = v;
        }
    }
    __syncthreads();
    if (t < EB) {
        int eg = e0 + t;
        if (eg < E) {
            float cw = s_red[0 * EB + t] + s_red[1 * EB + t] +
                       s_red[2 * EB + t] + s_red[3 * EB + t];
            int r = s_row[t];
            #pragma unroll
            for (int q = 0; q < 3; q++) {
                float tr = s_cd2[t * 3 + q] * cw;
                tr = fminf(fmaxf(tr, -10.0f), 10.0f);
                atomicAdd(&g_tsum[r * 3 + q], tr);
            }
            atomicAdd(&g_cnt[r], 1.0f);
        }
    }
}

extern "C" void kernel_launch(void* const* d_in, const int* in_sizes, int n_in,
                              void* d_out, int out_size) {
    const float* h     = (const float*)d_in[0];
    const int*   ei    = (const int*)d_in[1];
    const float* coord = (const float*)d_in[2];
    const float* We1  = (const float*)d_in[3];
    const float* be1  = (const float*)d_in[4];
    const float* We2  = (const float*)d_in[5];
    const float* be2  = (const float*)d_in[6];
    const float* Watt = (const float*)d_in[7];
    const float* batt = (const float*)d_in[8];
    const float* Wc1  = (const float*)d_in[9];
    const float* bc1  = (const float*)d_in[10];
    const float* Wc2  = (const float*)d_in[11];
    const float* Wn1  = (const float*)d_in[12];
    const float* bn1  = (const float*)d_in[13];
    const float* Wn2  = (const float*)d_in[14];
    const float* bn2  = (const float*)d_in[15];

    int N = in_sizes[0] / D;
    int E = in_sizes[1] / 2;

    float* out   = (float*)d_out;
    float* out_h = out;
    float* out_c = out + (size_t)N * D;
    float* out_e = out_c + (size_t)N * 3;

    cudaFuncSetAttribute(edge_tc_kernel, cudaFuncAttributeMaxDynamicSharedMemorySize, SMEM_EDGE);
    cudaFuncSetAttribute(node_tc_kernel, cudaFuncAttributeMaxDynamicSharedMemorySize, SMEM_NODE);

    zero_kernel<<<1024, 256>>>(N);
    prep_kernel<<<64, 512>>>(We1, We2, Wc1, Wn1, Wn2);

    int nb = E / TM;
    int e_main = nb * TM;
    int rem = E - e_main;
    if (nb > 0)
        edge_tc_kernel<<<nb, 256, SMEM_EDGE>>>(h, ei, coord, be1, be2,
                                               Watt, batt, bc1, Wc2, out_e, E);
    if (rem > 0)
        edge_rem_kernel<<<(rem + EB - 1) / EB, 128>>>(h, ei, coord, We1, be1, We2, be2,
                                                      Watt, batt, Wc1, bc1, Wc2,
                                                      out_e, E, e_main);
    node_tc_kernel<<<(N + TM - 1) / TM, 256, SMEM_NODE>>>(h, coord, bn1, bn2,
                                                          out_h, out_c, N);
}

// round 7
// speedup vs baseline: 1.9834x; 1.1615x over previous
#include <cuda_runtime.h>
#include <cuda_bf16.h>

#define D 128
#define MAXN 50176
#define TM 128
#define NB 16384   // bytes per B buffer (128x64 bf16)

typedef unsigned uns;

__device__ float g_agg[MAXN * D];
__device__ float g_tsum[MAXN * 3];
__device__ float g_cnt[MAXN];

// prepped W^T bf16 hi/lo: [chunk][n=128][kc=64]
__device__ __nv_bfloat16 g_W1H[4 * 8192], g_W1L[4 * 8192];
__device__ __nv_bfloat16 g_W2H[2 * 8192], g_W2L[2 * 8192];
__device__ __nv_bfloat16 g_WcH[2 * 8192], g_WcL[2 * 8192];
__device__ __nv_bfloat16 g_N1H[4 * 8192], g_N1L[4 * 8192];
__device__ __nv_bfloat16 g_N2H[2 * 8192], g_N2L[2 * 8192];
__device__ float g_W1last[128];

__device__ __forceinline__ float silu_f(float x) { return x / (1.0f + __expf(-x)); }
__device__ __forceinline__ uns sw128(uns o) { return o ^ ((o >> 3) & 0x70); }

__device__ __forceinline__ uns smem_u32(const void* p) {
    uns a;
    asm("{ .reg .u64 t; cvta.to.shared.u64 t, %1; cvt.u32.u64 %0, t; }" : "=r"(a) : "l"(p));
    return a;
}
__device__ __forceinline__ void split2(float a, float b, uns& hi, uns& lo) {
    uns p;
    asm("cvt.rn.satfinite.bf16x2.f32 %0, %1, %2;" : "=r"(p) : "f"(b), "f"(a));
    float f0 = __uint_as_float(p << 16);
    float f1 = __uint_as_float(p & 0xFFFF0000u);
    uns q;
    asm("cvt.rn.satfinite.bf16x2.f32 %0, %1, %2;" : "=r"(q) : "f"(b - f1), "f"(a - f0));
    hi = p; lo = q;
}
__device__ __forceinline__ void ldm_x2(uns r[2], uns addr) {
    asm volatile("ldmatrix.sync.aligned.m8n8.x2.shared.b16 {%0,%1}, [%2];"
        : "=r"(r[0]), "=r"(r[1]) : "r"(addr));
}
__device__ __forceinline__ void mma16816(float c[4], const uns a[4], const uns b[2]) {
    asm volatile("mma.sync.aligned.m16n8k16.row.col.f32.bf16.bf16.f32 "
        "{%0,%1,%2,%3}, {%4,%5,%6,%7}, {%8,%9}, {%0,%1,%2,%3};"
        : "+f"(c[0]), "+f"(c[1]), "+f"(c[2]), "+f"(c[3])
        : "r"(a[0]), "r"(a[1]), "r"(a[2]), "r"(a[3]), "r"(b[0]), "r"(b[1]));
}

// ------------------------------------------------------------------
__global__ void __launch_bounds__(256) zero_kernel(int N) {
    int i = blockIdx.x * blockDim.x + threadIdx.x;
    int stride = gridDim.x * blockDim.x;
    for (int k = i; k < N * D; k += stride) g_agg[k] = 0.0f;
    for (int k = i; k < N * 3; k += stride) g_tsum[k] = 0.0f;
    for (int k = i; k < N; k += stride) g_cnt[k] = 0.0f;
}

__global__ void __launch_bounds__(512) prep_kernel(
    const float* __restrict__ We1, const float* __restrict__ We2,
    const float* __restrict__ Wc1, const float* __restrict__ Wn1,
    const float* __restrict__ Wn2)
{
    int id = blockIdx.x * blockDim.x + threadIdx.x;  // 0..32767
    int c = id >> 13, r = id & 8191, n = r >> 6, kc = r & 63;
    int src = (c * 64 + kc) * 128 + n;
    {
        float f = We1[src];
        __nv_bfloat16 hv = __float2bfloat16(f);
        g_W1H[id] = hv; g_W1L[id] = __float2bfloat16(f - __bfloat162float(hv));
        float fn = Wn1[src];
        __nv_bfloat16 hn = __float2bfloat16(fn);
        g_N1H[id] = hn; g_N1L[id] = __float2bfloat16(fn - __bfloat162float(hn));
    }
    if (id < 2 * 8192) {
        float f = We2[src];
        __nv_bfloat16 hv = __float2bfloat16(f);
        g_W2H[id] = hv; g_W2L[id] = __float2bfloat16(f - __bfloat162float(hv));
        float g = Wc1[src];
        __nv_bfloat16 hg = __float2bfloat16(g);
        g_WcH[id] = hg; g_WcL[id] = __float2bfloat16(g - __bfloat162float(hg));
        float fn = Wn2[src];
        __nv_bfloat16 hn = __float2bfloat16(fn);
        g_N2H[id] = hn; g_N2L[id] = __float2bfloat16(fn - __bfloat162float(hn));
    }
    if (id < 128) g_W1last[id] = We1[256 * 128 + id];
}

// ---- common macros (t, su, smB, b_row, acc, af, alf in scope) ----
#define LOAD_B(gH, gL, c, buf)                                                \
    for (int i = t; i < 1024; i += 256) {                                     \
        uns dst = sw128((uns)((i >> 3) * 128 + (i & 7) * 16));                \
        *(uint4*)(smB + (buf) * NB + dst) = __ldg((const uint4*)(gH) + (c) * 1024 + i); \
        *(uint4*)(smB + 2 * NB + (buf) * NB + dst) = __ldg((const uint4*)(gL) + (c) * 1024 + i); \
    }

#define MMA_NT(ah, al, bufb)                                                  \
    _Pragma("unroll")                                                         \
    for (int nt = 0; nt < 16; nt++) {                                         \
        uns bh[2], bl[2];                                                     \
        uns bsw = sw128(b_row + (uns)(nt * 1024) + (uns)(ks * 32));           \
        ldm_x2(bh, su + (bufb) * NB + bsw);                                   \
        ldm_x2(bl, su + 2 * NB + (bufb) * NB + bsw);                          \
        mma16816(acc[nt], ah, bh);                                            \
        mma16816(acc[nt], al, bh);                                            \
        mma16816(acc[nt], ah, bl);                                            \
    }

#define ACC_ZERO()                                                            \
    _Pragma("unroll")                                                         \
    for (int nt = 0; nt < 16; nt++)                                           \
        _Pragma("unroll")                                                     \
        for (int j = 0; j < 4; j++) acc[nt][j] = 0.0f;

// layer with A fragments already in registers (af/alf[8][4]); nch must be literal
#define RUN_LAYER_REG(gH, gL, nch)                                            \
    {                                                                         \
        ACC_ZERO();                                                           \
        _Pragma("unroll")                                                     \
        for (int c = 0; c < (nch); c++) {                                     \
            if (c == 0) { LOAD_B(gH, gL, 0, 0); }                             \
            __syncthreads();                                                  \
            if (c + 1 < (nch)) { LOAD_B(gH, gL, c + 1, (c + 1) & 1); }        \
            const int bufb = c & 1;                                           \
            _Pragma("unroll")                                                 \
            for (int ks = 0; ks < 4; ks++) {                                  \
                MMA_NT(af[c * 4 + ks], alf[c * 4 + ks], bufb);                \
            }                                                                 \
        }                                                                     \
    }

// load A frags for one k-tile from two global row pointers
#define A_FRAGS_FROM_GLOBAL(pA, pB, k0, ah, al)                               \
    {                                                                         \
        float2 vA0 = *(const float2*)((pA) + (k0));                           \
        float2 vA1 = *(const float2*)((pA) + (k0) + 8);                       \
        float2 vB0 = *(const float2*)((pB) + (k0));                           \
        float2 vB1 = *(const float2*)((pB) + (k0) + 8);                       \
        split2(vA0.x, vA0.y, ah[0], al[0]);                                   \
        split2(vB0.x, vB0.y, ah[1], al[1]);                                   \
        split2(vA1.x, vA1.y, ah[2], al[2]);                                   \
        split2(vB1.x, vB1.y, ah[3], al[3]);                                   \
    }

__global__ void __launch_bounds__(256, 1) edge_tc_kernel(
    const float* __restrict__ h, const int* __restrict__ ei,
    const float* __restrict__ coord,
    const float* __restrict__ be1, const float* __restrict__ be2,
    const float* __restrict__ Watt, const float* __restrict__ batt,
    const float* __restrict__ bc1, const float* __restrict__ Wc2,
    float* __restrict__ out_ef, int E)
{
    extern __shared__ __align__(1024) char smB[];  // [h0][h1][l0][l1] 16KB each
    __shared__ int s_row[TM], s_col[TM];
    __shared__ float s_rad[TM], s_cd[TM * 3];

    const uns su = smem_u32(smB);
    const int t = threadIdx.x;
    const int w = t >> 5, l = t & 31;
    const int g = l >> 2, tq = l & 3;
    const int e0 = blockIdx.x * TM;
    const uns b_row = (uns)((l & 7) * 128 + ((l >> 3) & 1) * 16);

    if (t < TM) {
        int e = min(e0 + t, E - 1);
        int r = ei[e], c = ei[(size_t)E + e];
        s_row[t] = r; s_col[t] = c;
        float dx = coord[r * 3 + 0] - coord[c * 3 + 0];
        float dy = coord[r * 3 + 1] - coord[c * 3 + 1];
        float dz = coord[r * 3 + 2] - coord[c * 3 + 2];
        s_cd[t * 3 + 0] = dx; s_cd[t * 3 + 1] = dy; s_cd[t * 3 + 2] = dz;
        s_rad[t] = dx * dx + dy * dy + dz * dz;
    }
    __syncthreads();

    const int r0 = w * 16 + g, r1 = r0 + 8;
    const bool v0 = (e0 + r0) < E, v1 = (e0 + r1) < E;

    float acc[16][4];
    uns af[8][4], alf[8][4];

    // ===== layer1: A direct from global =====
    {
        const float* pR0 = h + (size_t)s_row[r0] * 128;
        const float* pC0 = h + (size_t)s_col[r0] * 128;
        const float* pR1 = h + (size_t)s_row[r1] * 128;
        const float* pC1 = h + (size_t)s_col[r1] * 128;
        ACC_ZERO();
        #pragma unroll
        for (int c = 0; c < 4; c++) {
            if (c == 0) { LOAD_B(g_W1H, g_W1L, 0, 0); }
            __syncthreads();
            if (c < 3) { LOAD_B(g_W1H, g_W1L, c + 1, (c + 1) & 1); }
            const float* pA = (c >> 1) ? pC0 : pR0;
            const float* pB = (c >> 1) ? pC1 : pR1;
            const int koff = (c & 1) * 64 + 2 * tq;
            const int bufb = c & 1;
            #pragma unroll
            for (int ks = 0; ks < 4; ks++) {
                uns ah[4], al[4];
                A_FRAGS_FROM_GLOBAL(pA, pB, koff + ks * 16, ah, al);
                MMA_NT(ah, al, bufb);
            }
        }
    }
    // epilogue1 -> frags
    {
        float rad0 = s_rad[r0], rad1 = s_rad[r1];
        #pragma unroll
        for (int nt = 0; nt < 16; nt++) {
            int c0 = nt * 8 + 2 * tq;
            float w0 = g_W1last[c0], w1 = g_W1last[c0 + 1];
            float b0 = __ldg(be1 + c0), b1 = __ldg(be1 + c0 + 1);
            float x0 = silu_f(acc[nt][0] + b0 + rad0 * w0);
            float x1 = silu_f(acc[nt][1] + b1 + rad0 * w1);
            float x2 = silu_f(acc[nt][2] + b0 + rad1 * w0);
            float x3 = silu_f(acc[nt][3] + b1 + rad1 * w1);
            int kt = nt >> 1, s = (nt & 1) * 2;
            split2(x0, x1, af[kt][s], alf[kt][s]);
            split2(x2, x3, af[kt][s + 1], alf[kt][s + 1]);
        }
    }

    // ===== layer2 + attention =====
    RUN_LAYER_REG(g_W2H, g_W2L, 2);
    {
        float d0 = 0.0f, d1 = 0.0f;
        #pragma unroll
        for (int nt = 0; nt < 16; nt++) {
            int c0 = nt * 8 + 2 * tq;
            float b0 = __ldg(be2 + c0), b1 = __ldg(be2 + c0 + 1);
            float wa0 = __ldg(Watt + c0), wa1 = __ldg(Watt + c0 + 1);
            acc[nt][0] = silu_f(acc[nt][0] + b0);
            acc[nt][1] = silu_f(acc[nt][1] + b1);
            acc[nt][2] = silu_f(acc[nt][2] + b0);
            acc[nt][3] = silu_f(acc[nt][3] + b1);
            d0 += acc[nt][0] * wa0 + acc[nt][1] * wa1;
            d1 += acc[nt][2] * wa0 + acc[nt][3] * wa1;
        }
        d0 += __shfl_xor_sync(0xffffffffu, d0, 1);
        d0 += __shfl_xor_sync(0xffffffffu, d0, 2);
        d1 += __shfl_xor_sync(0xffffffffu, d1, 1);
        d1 += __shfl_xor_sync(0xffffffffu, d1, 2);
        float bt = __ldg(batt);
        float att0 = 1.0f / (1.0f + __expf(-(d0 + bt)));
        float att1 = 1.0f / (1.0f + __expf(-(d1 + bt)));
        int ra = s_row[r0], rb = s_row[r1];
        float* oA = out_ef + (size_t)(e0 + r0) * 128;
        float* oB = out_ef + (size_t)(e0 + r1) * 128;
        #pragma unroll
        for (int nt = 0; nt < 16; nt++) {
            int c0 = nt * 8 + 2 * tq;
            float x0 = acc[nt][0] * att0, x1 = acc[nt][1] * att0;
            float x2 = acc[nt][2] * att1, x3 = acc[nt][3] * att1;
            if (v0) {
                *(float2*)(oA + c0) = make_float2(x0, x1);
                atomicAdd(&g_agg[(size_t)ra * 128 + c0], x0);
                atomicAdd(&g_agg[(size_t)ra * 128 + c0 + 1], x1);
            }
            if (v1) {
                *(float2*)(oB + c0) = make_float2(x2, x3);
                atomicAdd(&g_agg[(size_t)rb * 128 + c0], x2);
                atomicAdd(&g_agg[(size_t)rb * 128 + c0 + 1], x3);
            }
            int kt = nt >> 1, s = (nt & 1) * 2;
            split2(x0, x1, af[kt][s], alf[kt][s]);
            split2(x2, x3, af[kt][s + 1], alf[kt][s + 1]);
        }
    }

    // ===== layer3 (coord) =====
    RUN_LAYER_REG(g_WcH, g_WcL, 2);
    {
        float d0 = 0.0f, d1 = 0.0f;
        #pragma unroll
        for (int nt = 0; nt < 16; nt++) {
            int c0 = nt * 8 + 2 * tq;
            float b0 = __ldg(bc1 + c0), b1 = __ldg(bc1 + c0 + 1);
            float wc0 = __ldg(Wc2 + c0), wc1 = __ldg(Wc2 + c0 + 1);
            d0 += silu_f(acc[nt][0] + b0) * wc0 + silu_f(acc[nt][1] + b1) * wc1;
            d1 += silu_f(acc[nt][2] + b0) * wc0 + silu_f(acc[nt][3] + b1) * wc1;
        }
        d0 += __shfl_xor_sync(0xffffffffu, d0, 1);
        d0 += __shfl_xor_sync(0xffffffffu, d0, 2);
        d1 += __shfl_xor_sync(0xffffffffu, d1, 1);
        d1 += __shfl_xor_sync(0xffffffffu, d1, 2);
        if (tq == 0) {
            #pragma unroll
            for (int i = 0; i < 2; i++) {
                int rr = i ? r1 : r0;
                bool vv = i ? v1 : v0;
                float cw = i ? d1 : d0;
                if (vv) {
                    int rn = s_row[rr];
                    #pragma unroll
                    for (int q = 0; q < 3; q++) {
                        float tr = s_cd[rr * 3 + q] * cw;
                        tr = fminf(fmaxf(tr, -10.0f), 10.0f);
                        atomicAdd(&g_tsum[rn * 3 + q], tr);
                    }
                    atomicAdd(&g_cnt[rn], 1.0f);
                }
            }
        }
    }
}

__global__ void __launch_bounds__(256, 1) node_tc_kernel(
    const float* __restrict__ h, const float* __restrict__ coord,
    const float* __restrict__ bn1, const float* __restrict__ bn2,
    float* __restrict__ out_h, float* __restrict__ out_c, int N)
{
    extern __shared__ __align__(1024) char smB[];
    const uns su = smem_u32(smB);
    const int t = threadIdx.x;
    const int w = t >> 5, l = t & 31;
    const int g = l >> 2, tq = l & 3;
    const int n0 = blockIdx.x * TM;
    const uns b_row = (uns)((l & 7) * 128 + ((l >> 3) & 1) * 16);

    const int r0 = w * 16 + g, r1 = r0 + 8;
    const int nA = min(n0 + r0, N - 1), nB = min(n0 + r1, N - 1);
    const bool v0 = (n0 + r0) < N, v1 = (n0 + r1) < N;

    float acc[16][4];
    uns af[8][4], alf[8][4];

    // layer1: chunks 0,1 from h; 2,3 from g_agg
    {
        const float* pH0 = h + (size_t)nA * 128;
        const float* pH1 = h + (size_t)nB * 128;
        const float* pG0 = g_agg + (size_t)nA * 128;
        const float* pG1 = g_agg + (size_t)nB * 128;
        ACC_ZERO();
        #pragma unroll
        for (int c = 0; c < 4; c++) {
            if (c == 0) { LOAD_B(g_N1H, g_N1L, 0, 0); }
            __syncthreads();
            if (c < 3) { LOAD_B(g_N1H, g_N1L, c + 1, (c + 1) & 1); }
            const float* pA = (c >> 1) ? pG0 : pH0;
            const float* pB = (c >> 1) ? pG1 : pH1;
            const int koff = (c & 1) * 64 + 2 * tq;
            const int bufb = c & 1;
            #pragma unroll
            for (int ks = 0; ks < 4; ks++) {
                uns ah[4], al[4];
                A_FRAGS_FROM_GLOBAL(pA, pB, koff + ks * 16, ah, al);
                MMA_NT(ah, al, bufb);
            }
        }
    }
    {
        #pragma unroll
        for (int nt = 0; nt < 16; nt++) {
            int c0 = nt * 8 + 2 * tq;
            float b0 = __ldg(bn1 + c0), b1 = __ldg(bn1 + c0 + 1);
            float x0 = silu_f(acc[nt][0] + b0);
            float x1 = silu_f(acc[nt][1] + b1);
            float x2 = silu_f(acc[nt][2] + b0);
            float x3 = silu_f(acc[nt][3] + b1);
            int kt = nt >> 1, s = (nt & 1) * 2;
            split2(x0, x1, af[kt][s], alf[kt][s]);
            split2(x2, x3, af[kt][s + 1], alf[kt][s + 1]);
        }
    }

    RUN_LAYER_REG(g_N2H, g_N2L, 2);
    {
        #pragma unroll
        for (int nt = 0; nt < 16; nt++) {
            int c0 = nt * 8 + 2 * tq;
            float b0 = __ldg(bn2 + c0), b1 = __ldg(bn2 + c0 + 1);
            if (v0) {
                float2 hv = *(const float2*)(h + (size_t)nA * 128 + c0);
                *(float2*)(out_h + (size_t)nA * 128 + c0) =
                    make_float2(hv.x + acc[nt][0] + b0, hv.y + acc[nt][1] + b1);
            }
            if (v1) {
                float2 hv = *(const float2*)(h + (size_t)nB * 128 + c0);
                *(float2*)(out_h + (size_t)nB * 128 + c0) =
                    make_float2(hv.x + acc[nt][2] + b0, hv.y + acc[nt][3] + b1);
            }
        }
    }

    if (t < TM) {
        int n = n0 + t;
        if (n < N) {
            float c = fmaxf(g_cnt[n], 1.0f);
            #pragma unroll
            for (int q = 0; q < 3; q++) {
                float m = g_tsum[n * 3 + q] / c;
                m = fminf(fmaxf(m, -10.0f), 10.0f);
                out_c[n * 3 + q] = coord[n * 3 + q] + m;
            }
        }
    }
}

extern "C" void kernel_launch(void* const* d_in, const int* in_sizes, int n_in,
                              void* d_out, int out_size) {
    const float* h     = (const float*)d_in[0];
    const int*   ei    = (const int*)d_in[1];
    const float* coord = (const float*)d_in[2];
    const float* We1  = (const float*)d_in[3];
    const float* be1  = (const float*)d_in[4];
    const float* We2  = (const float*)d_in[5];
    const float* be2  = (const float*)d_in[6];
    const float* Watt = (const float*)d_in[7];
    const float* batt = (const float*)d_in[8];
    const float* Wc1  = (const float*)d_in[9];
    const float* bc1  = (const float*)d_in[10];
    const float* Wc2  = (const float*)d_in[11];
    const float* Wn1  = (const float*)d_in[12];
    const float* bn1  = (const float*)d_in[13];
    const float* Wn2  = (const float*)d_in[14];
    const float* bn2  = (const float*)d_in[15];

    int N = in_sizes[0] / D;
    int E = in_sizes[1] / 2;

    float* out   = (float*)d_out;
    float* out_h = out;
    float* out_c = out + (size_t)N * D;
    float* out_e = out_c + (size_t)N * 3;

    const int SMEM = 4 * NB;
    cudaFuncSetAttribute(edge_tc_kernel, cudaFuncAttributeMaxDynamicSharedMemorySize, SMEM);
    cudaFuncSetAttribute(node_tc_kernel, cudaFuncAttributeMaxDynamicSharedMemorySize, SMEM);

    zero_kernel<<<1024, 256>>>(N);
    prep_kernel<<<64, 512>>>(We1, We2, Wc1, Wn1, Wn2);

    int nbe = (E + TM - 1) / TM;
    edge_tc_kernel<<<nbe, 256, SMEM>>>(h, ei, coord, be1, be2,
                                       Watt, batt, bc1, Wc2, out_e, E);
    int nbn = (N + TM - 1) / TM;
    node_tc_kernel<<<nbn, 256, SMEM>>>(h, coord, bn1, bn2, out_h, out_c, N);
}